// round 12
// baseline (speedup 1.0000x reference)
#include <cuda_runtime.h>
#include <math.h>
#include <stdint.h>

#define SEQ    1024
#define CDIM   768
#define BATCH  8
#define NHEADS 12
#define HD     64
#define BHN    (BATCH*NHEADS)
#define SCALEF 0.125f

// Scratch. q/k in [B,H,N,hd] with hd-permuted storage; v natural; ao k-permuted.
__device__ float g_q[(size_t)BHN*SEQ*HD];
__device__ float g_k[(size_t)BHN*SEQ*HD];
__device__ float g_v[(size_t)BHN*SEQ*HD];
__device__ float g_ao[(size_t)BATCH*SEQ*CDIM];
__device__ float g_xr[(size_t)BATCH*SEQ*CDIM];     // x, tf32, col k-perm
__device__ float g_wqr[(size_t)3*CDIM*CDIM];       // qkv_w, tf32, col k-perm, q/k rows perm
__device__ float g_wpr[(size_t)CDIM*CDIM];         // proj_w, tf32, col k-perm
__device__ float g_bqkv[3*CDIM];                   // qkv_b, q/k sections row-perm

__device__ __forceinline__ unsigned f2tf32(float f) {
    unsigned u;
    asm("cvt.rna.tf32.f32 %0, %1;" : "=r"(u) : "f"(f));
    return u;
}
__device__ __forceinline__ uint32_t smem_u32(const void* p) {
    uint32_t a;
    asm("{ .reg .u64 t; cvta.to.shared.u64 t, %1; cvt.u32.u64 %0, t; }"
        : "=r"(a) : "l"(p));
    return a;
}
__device__ __forceinline__ void cp16(uint32_t dst, const void* src) {
    asm volatile("cp.async.cg.shared.global [%0], [%1], 16;"
                 :: "r"(dst), "l"(__cvta_generic_to_global(src)) : "memory");
}
__device__ __forceinline__ void cp_commit() {
    asm volatile("cp.async.commit_group;" ::: "memory");
}
template<int N>
__device__ __forceinline__ void cp_wait() {
    asm volatile("cp.async.wait_group %0;" :: "n"(N) : "memory");
}
__device__ __forceinline__ void mma_tf32(float c[4], const unsigned a[4],
                                         unsigned b0, unsigned b1) {
    asm volatile(
        "mma.sync.aligned.m16n8k8.row.col.f32.tf32.tf32.f32 "
        "{%0,%1,%2,%3}, {%4,%5,%6,%7}, {%8,%9}, {%0,%1,%2,%3};\n"
        : "+f"(c[0]), "+f"(c[1]), "+f"(c[2]), "+f"(c[3])
        : "r"(a[0]), "r"(a[1]), "r"(a[2]), "r"(a[3]), "r"(b0), "r"(b1));
}
// storage position j within an 8-group holds logical element invp(j)
__device__ __forceinline__ int invp(int j) { return ((j & 1) << 2) | (j >> 1); }

// ---------------------------------------------------------------------------
// Fused pre-round + permute for x, qkv_w, proj_w (8-col groups) + bias perm.
// Group order: [x | qkv_w | proj_w], then 3*CDIM bias slots.
// ---------------------------------------------------------------------------
#define GX (BATCH*SEQ*CDIM/8)
#define GW (3*CDIM*CDIM/8)
#define GP (CDIM*CDIM/8)
__global__ void pre_all(const float* __restrict__ x, const float* __restrict__ qkv_w,
                        const float* __restrict__ proj_w, const float* __restrict__ qkv_b)
{
    int i = blockIdx.x * blockDim.x + threadIdx.x;
    if (i < GX + GW + GP) {
        const float* src;
        float* dst;
        int li, which;
        if (i < GX)            { src = x;      dst = g_xr;  li = i;            which = 0; }
        else if (i < GX + GW)  { src = qkv_w;  dst = g_wqr; li = i - GX;       which = 1; }
        else                   { src = proj_w; dst = g_wpr; li = i - GX - GW;  which = 2; }
        const int gpr = CDIM >> 3;
        const int row = li / gpr, cg = li - row * gpr;
        int srow = row;
        if (which == 1 && row < 2 * CDIM) srow = (row & ~7) | invp(row & 7);
        const float* s = src + (size_t)srow * CDIM + cg * 8;
        float4 f0 = *(const float4*)(s);
        float4 f1 = *(const float4*)(s + 4);
        uint4 u0, u1;
        u0.x = f2tf32(f0.x); u0.y = f2tf32(f1.x); u0.z = f2tf32(f0.y); u0.w = f2tf32(f1.y);
        u1.x = f2tf32(f0.z); u1.y = f2tf32(f1.z); u1.z = f2tf32(f0.w); u1.w = f2tf32(f1.w);
        uint4* d = (uint4*)(dst + (size_t)row * CDIM + cg * 8);
        d[0] = u0; d[1] = u1;
    } else {
        int j = i - (GX + GW + GP);
        if (j < 3 * CDIM) {
            int sj = (j < 2 * CDIM) ? ((j & ~7) | invp(j & 7)) : j;
            g_bqkv[j] = qkv_b[sj];
        }
    }
}

// ---------------------------------------------------------------------------
// Tensor-core GEMM (mma.sync tf32), cp.async 2-stage, ONE barrier per K-tile.
// BM=BN=128, BK=32, 8 warps (2x4), warp tile 64x32. Row stride 40 words.
// MODE 0: A=g_xr, W=g_wqr, bias=g_bqkv, scatter tf32-rounded q/k/v.
// MODE 1: A=g_ao, W=g_wpr, plain fp32 output.
// ---------------------------------------------------------------------------
template<int MODE>
__global__ __launch_bounds__(256, 2)
void gemm_tc(const float* __restrict__ biasp, float* __restrict__ Cout,
             int M, int N, int K)
{
    extern __shared__ unsigned gsm[];   // 2 stages * (5120 A + 5120 B)
    const uint32_t sb = smem_u32(gsm);

    const int tid  = threadIdx.x;
    const int lane = tid & 31, warp = tid >> 5;
    const int g    = lane >> 2, tig = lane & 3;
    const int wm   = (warp >> 2) * 64;
    const int wn   = (warp & 3) * 32;
    const int m0   = blockIdx.y * 128;
    const int n0   = blockIdx.x * 128;

    const float* Ag = ((MODE == 1) ? (const float*)g_ao : (const float*)g_xr)
                      + (size_t)m0 * K;
    const float* Wg = ((MODE == 1) ? (const float*)g_wpr : (const float*)g_wqr)
                      + (size_t)n0 * K;
    const float* bias = (MODE == 0) ? (const float*)g_bqkv : biasp;

    const int NT = K / 32;

    auto issue = [&](int t, int s) {
        const int kb = t * 32;
        const uint32_t abase = sb + (s * 10240) * 4;
        const uint32_t wbase = abase + 5120 * 4;
        #pragma unroll
        for (int j = 0; j < 4; j++) {
            const int idx = tid + 256 * j;
            const int r = idx >> 3, c = (idx & 7) << 2;
            cp16(abase + (r * 40 + c) * 4, Ag + (size_t)r * K + kb + c);
            cp16(wbase + (r * 40 + c) * 4, Wg + (size_t)r * K + kb + c);
        }
        cp_commit();
    };

    float acc[4][4][4];
    #pragma unroll
    for (int mi = 0; mi < 4; mi++)
        #pragma unroll
        for (int nj = 0; nj < 4; nj++)
            #pragma unroll
            for (int c = 0; c < 4; c++) acc[mi][nj][c] = 0.f;

    issue(0, 0);
    for (int t = 0; t < NT; t++) {
        const int s = t & 1;
        cp_wait<0>();          // stage t (the only pending group) complete
        __syncthreads();       // publish; also proves stage s^1 fully consumed
        if (t + 1 < NT) issue(t + 1, s ^ 1);   // overlaps compute below

        const unsigned* Asu = gsm + s * 10240;
        const unsigned* Wsu = Asu + 5120;
        #pragma unroll
        for (int ks = 0; ks < 4; ks++) {
            const int kc = 8 * ks + 2 * tig;
            uint2 bfr[4];
            #pragma unroll
            for (int nj = 0; nj < 4; nj++)
                bfr[nj] = *(const uint2*)&Wsu[(wn + 8*nj + g) * 40 + kc];
            #pragma unroll
            for (int mi = 0; mi < 4; mi++) {
                uint2 a01 = *(const uint2*)&Asu[(wm + 16*mi + g    ) * 40 + kc];
                uint2 a23 = *(const uint2*)&Asu[(wm + 16*mi + 8 + g) * 40 + kc];
                unsigned afr[4] = {a01.x, a23.x, a01.y, a23.y};
                #pragma unroll
                for (int nj = 0; nj < 4; nj++)
                    mma_tf32(acc[mi][nj], afr, bfr[nj].x, bfr[nj].y);
            }
        }
    }

    float2 bv[4];
    int colv[4];
    #pragma unroll
    for (int nj = 0; nj < 4; nj++) {
        const int col = n0 + wn + 8*nj + 2*tig;
        colv[nj] = col;
        bv[nj].x = bias[col];
        bv[nj].y = bias[col + 1];
    }

    if (MODE == 0) {
        const int tsel = n0 / CDIM;
        float* dst = (tsel == 0) ? g_q : (tsel == 1) ? g_k : g_v;
        const int b = m0 >> 10;
        #pragma unroll
        for (int mi = 0; mi < 4; mi++) {
            #pragma unroll
            for (int rr = 0; rr < 2; rr++) {
                const int row = m0 + wm + 16*mi + g + 8*rr;
                const int n   = row & (SEQ - 1);
                #pragma unroll
                for (int nj = 0; nj < 4; nj++) {
                    const int rem = colv[nj] - tsel * CDIM;
                    const int h = rem >> 6;
                    const int d = rem & 63;
                    float2 v;
                    v.x = __uint_as_float(f2tf32(acc[mi][nj][2*rr + 0] + bv[nj].x));
                    v.y = __uint_as_float(f2tf32(acc[mi][nj][2*rr + 1] + bv[nj].y));
                    *(float2*)&dst[(((size_t)b * NHEADS + h) * SEQ + n) * HD + d] = v;
                }
            }
        }
    } else {
        #pragma unroll
        for (int mi = 0; mi < 4; mi++) {
            #pragma unroll
            for (int rr = 0; rr < 2; rr++) {
                const int row = m0 + wm + 16*mi + g + 8*rr;
                #pragma unroll
                for (int nj = 0; nj < 4; nj++) {
                    float2 v;
                    v.x = acc[mi][nj][2*rr + 0] + bv[nj].x;
                    v.y = acc[mi][nj][2*rr + 1] + bv[nj].y;
                    *(float2*)&Cout[(size_t)row * N + colv[nj]] = v;
                }
            }
        }
    }
}

// ---------------------------------------------------------------------------
// Fused flash attention: 512 threads = 16 warps, 256 Q-rows per CTA.
// Warp w owns rows 16w..16w+15; K/V tiles shared by all warps (half traffic).
// One barrier per K-tile. SMEM words: QP[0,18432) | stage s at 18432+s*9216.
// ---------------------------------------------------------------------------
#define NKT (SEQ/64)
__global__ __launch_bounds__(512)
void attn_tc()
{
    extern __shared__ unsigned sm[];
    unsigned* QPs = sm;
    const uint32_t sb = smem_u32(sm);

    const int tid  = threadIdx.x;
    const int lane = tid & 31, warp = tid >> 5;
    const int g    = lane >> 2, tig = lane & 3;
    const int bh   = blockIdx.y;
    const int qt   = blockIdx.x;

    const int p0 = ((tig & 1) ? 4 : 0) + (tig >> 1);

    const float* qg = g_q + (size_t)bh * SEQ * HD + (size_t)qt * 256 * HD;
    const float* kg = g_k + (size_t)bh * SEQ * HD;
    const float* vg = g_v + (size_t)bh * SEQ * HD;

    auto issue_kv = [&](int kt, int s) {
        const float* kp = kg + (size_t)kt * 64 * HD;
        const float* vp = vg + (size_t)kt * 64 * HD;
        const uint32_t kb = sb + (18432 + s * 9216) * 4;
        const uint32_t vb = kb + 4608 * 4;
        #pragma unroll
        for (int j = 0; j < 2; j++) {
            const int idx = tid + 512 * j;
            const int r = idx >> 4, c = (idx & 15) << 2;
            cp16(kb + (r * 72 + c) * 4, kp + (size_t)r * HD + c);
            cp16(vb + (r * 72 + c) * 4, vp + (size_t)r * HD + c);
        }
        cp_commit();
    };

    // Q: 256x64 = 4096 16B-chunks, 8 per thread
    #pragma unroll
    for (int j = 0; j < 8; j++) {
        const int idx = tid + 512 * j;
        const int r = idx >> 4, c = (idx & 15) << 2;
        cp16(sb + (r * 72 + c) * 4, qg + (size_t)r * HD + c);
    }
    cp_commit();
    issue_kv(0, 0);
    cp_wait<0>();
    __syncthreads();

    // Q fragments register-resident (warp-private rows; no further sync needed)
    unsigned aq[8][4];
    {
        const int r = 16 * warp;
        #pragma unroll
        for (int ks = 0; ks < 8; ks++) {
            const int kc = 8*ks + 2*tig;
            uint2 q01 = *(const uint2*)&QPs[(r + g    ) * 72 + kc];
            uint2 q23 = *(const uint2*)&QPs[(r + 8 + g) * 72 + kc];
            aq[ks][0] = q01.x; aq[ks][1] = q23.x; aq[ks][2] = q01.y; aq[ks][3] = q23.y;
        }
    }

    float o[8][4];
    #pragma unroll
    for (int nj = 0; nj < 8; nj++)
        #pragma unroll
        for (int c = 0; c < 4; c++) o[nj][c] = 0.f;
    float m0r = -1e30f, m1r = -1e30f, l0 = 0.f, l1 = 0.f;

    for (int kt = 0; kt < NKT; kt++) {
        const int s = kt & 1;
        if (kt > 0) {
            cp_wait<0>();      // kv(kt) (sole pending group) complete
            __syncthreads();   // publish; proves stage s^1 consumed at kt-1
        }
        if (kt + 1 < NKT) issue_kv(kt + 1, s ^ 1);

        const unsigned* Ks = sm + 18432 + s * 9216;
        const unsigned* Vs = Ks + 4608;

        float sc[8][4];
        #pragma unroll
        for (int nj = 0; nj < 8; nj++)
            #pragma unroll
            for (int c = 0; c < 4; c++) sc[nj][c] = 0.f;

        #pragma unroll
        for (int ks = 0; ks < 8; ks++) {
            const int kc = 8*ks + 2*tig;
            #pragma unroll
            for (int nj = 0; nj < 8; nj++) {
                uint2 b = *(const uint2*)&Ks[(8*nj + g) * 72 + kc];
                mma_tf32(sc[nj], aq[ks], b.x, b.y);
            }
        }

        float rm0 = -1e30f, rm1 = -1e30f;
        #pragma unroll
        for (int nj = 0; nj < 8; nj++) {
            sc[nj][0] *= SCALEF; sc[nj][1] *= SCALEF;
            sc[nj][2] *= SCALEF; sc[nj][3] *= SCALEF;
            rm0 = fmaxf(rm0, fmaxf(sc[nj][0], sc[nj][1]));
            rm1 = fmaxf(rm1, fmaxf(sc[nj][2], sc[nj][3]));
        }
        rm0 = fmaxf(rm0, __shfl_xor_sync(0xffffffffu, rm0, 1));
        rm0 = fmaxf(rm0, __shfl_xor_sync(0xffffffffu, rm0, 2));
        rm1 = fmaxf(rm1, __shfl_xor_sync(0xffffffffu, rm1, 1));
        rm1 = fmaxf(rm1, __shfl_xor_sync(0xffffffffu, rm1, 2));

        const float mn0 = fmaxf(m0r, rm0);
        const float mn1 = fmaxf(m1r, rm1);
        const float cr0 = __expf(m0r - mn0);
        const float cr1 = __expf(m1r - mn1);
        float rs0 = 0.f, rs1 = 0.f;
        #pragma unroll
        for (int nj = 0; nj < 8; nj++) {
            sc[nj][0] = __expf(sc[nj][0] - mn0);
            sc[nj][1] = __expf(sc[nj][1] - mn0);
            sc[nj][2] = __expf(sc[nj][2] - mn1);
            sc[nj][3] = __expf(sc[nj][3] - mn1);
            rs0 += sc[nj][0] + sc[nj][1];
            rs1 += sc[nj][2] + sc[nj][3];
        }
        rs0 += __shfl_xor_sync(0xffffffffu, rs0, 1);
        rs0 += __shfl_xor_sync(0xffffffffu, rs0, 2);
        rs1 += __shfl_xor_sync(0xffffffffu, rs1, 1);
        rs1 += __shfl_xor_sync(0xffffffffu, rs1, 2);
        l0 = l0 * cr0 + rs0;  m0r = mn0;
        l1 = l1 * cr1 + rs1;  m1r = mn1;
        #pragma unroll
        for (int nj = 0; nj < 8; nj++) {
            o[nj][0] *= cr0; o[nj][1] *= cr0;
            o[nj][2] *= cr1; o[nj][3] *= cr1;
        }

        // stage P at permuted n-positions (warp-private rows)
        {
            const int r0 = 16*warp + g;
            #pragma unroll
            for (int nj = 0; nj < 8; nj++) {
                QPs[ r0      * 72 + 8*nj + p0    ] = f2tf32(sc[nj][0]);
                QPs[ r0      * 72 + 8*nj + p0 + 2] = f2tf32(sc[nj][1]);
                QPs[(r0 + 8) * 72 + 8*nj + p0    ] = f2tf32(sc[nj][2]);
                QPs[(r0 + 8) * 72 + 8*nj + p0 + 2] = f2tf32(sc[nj][3]);
            }
        }
        __syncwarp();

        #pragma unroll
        for (int ks = 0; ks < 8; ks++) {
            const int kc = 8*ks + 2*tig;
            uint2 p01 = *(const uint2*)&QPs[(16*warp + g    ) * 72 + kc];
            uint2 p23 = *(const uint2*)&QPs[(16*warp + 8 + g) * 72 + kc];
            unsigned pa[4] = {p01.x, p23.x, p01.y, p23.y};
            #pragma unroll
            for (int nj = 0; nj < 8; nj++) {
                const unsigned b0 = Vs[(8*ks + tig    ) * 72 + 8*nj + g];
                const unsigned b1 = Vs[(8*ks + tig + 4) * 72 + 8*nj + g];
                mma_tf32(o[nj], pa, b0, b1);
            }
        }
        __syncthreads();   // all warps done with stage s before kt+1 overwrites s^1's pair
    }

    // normalize + write g_ao at k-permuted positions (tf32-rounded, for proj)
    const int b = bh / NHEADS, h = bh % NHEADS;
    const float inv0 = 1.f / l0, inv1 = 1.f / l1;
    const int r0 = qt * 256 + 16*warp + g;
    float* ao0 = g_ao + ((size_t)b * SEQ + r0    ) * CDIM + h * HD;
    float* ao1 = g_ao + ((size_t)b * SEQ + r0 + 8) * CDIM + h * HD;
    #pragma unroll
    for (int nj = 0; nj < 8; nj++) {
        const int q0 = 8*nj + p0, q1 = 8*nj + p0 + 2;
        ao0[q0] = __uint_as_float(f2tf32(o[nj][0] * inv0));
        ao0[q1] = __uint_as_float(f2tf32(o[nj][1] * inv0));
        ao1[q0] = __uint_as_float(f2tf32(o[nj][2] * inv1));
        ao1[q1] = __uint_as_float(f2tf32(o[nj][3] * inv1));
    }
}

// ---------------------------------------------------------------------------
// Inputs (metadata order): x, qkv_w, qkv_b, proj_w, proj_b, H, W
// ---------------------------------------------------------------------------
extern "C" void kernel_launch(void* const* d_in, const int* in_sizes, int n_in,
                              void* d_out, int out_size)
{
    (void)in_sizes; (void)n_in; (void)out_size;
    const float* x      = (const float*)d_in[0];
    const float* qkv_w  = (const float*)d_in[1];
    const float* qkv_b  = (const float*)d_in[2];
    const float* proj_w = (const float*)d_in[3];
    const float* proj_b = (const float*)d_in[4];
    float* out = (float*)d_out;

    const int smem_gemm = 2 * 10240 * (int)sizeof(unsigned);        // 81920 B
    const int smem_attn = (18432 + 2 * 9216) * (int)sizeof(unsigned); // 147456 B
    cudaFuncSetAttribute(gemm_tc<0>, cudaFuncAttributeMaxDynamicSharedMemorySize, smem_gemm);
    cudaFuncSetAttribute(gemm_tc<1>, cudaFuncAttributeMaxDynamicSharedMemorySize, smem_gemm);
    cudaFuncSetAttribute(attn_tc,    cudaFuncAttributeMaxDynamicSharedMemorySize, smem_attn);

    // 0) fused pre-round + permute (x, qkv_w, proj_w, bias) in one launch
    {
        const int ntot = GX + GW + GP + 3 * CDIM;
        pre_all<<<(ntot + 255) / 256, 256>>>(x, qkv_w, proj_w, qkv_b);
    }

    // 1) QKV GEMM + bias -> per-head q/k/v (q/k d-permuted via W-row perm)
    gemm_tc<0><<<dim3(3 * CDIM / 128, (BATCH * SEQ) / 128), 256, smem_gemm>>>(
        nullptr, nullptr, BATCH * SEQ, 3 * CDIM, CDIM);

    // 2) fused flash attention -> g_ao (k-permuted, tf32-rounded)
    attn_tc<<<dim3(SEQ / 256, BHN), 512, smem_attn>>>();

    // 3) proj GEMM + bias -> d_out (fp32, natural layout)
    gemm_tc<1><<<dim3(CDIM / 128, (BATCH * SEQ) / 128), 256, smem_gemm>>>(
        proj_b, out, BATCH * SEQ, CDIM, CDIM);
}

// round 15
// speedup vs baseline: 1.5357x; 1.5357x over previous
#include <cuda_runtime.h>
#include <math.h>
#include <stdint.h>

#define SEQ    1024
#define CDIM   768
#define BATCH  8
#define NHEADS 12
#define HD     64
#define BHN    (BATCH*NHEADS)
#define SCALEF 0.125f

// Scratch. q/k in [B,H,N,hd] with hd-permuted storage; v natural; ao k-permuted.
__device__ float g_q[(size_t)BHN*SEQ*HD];
__device__ float g_k[(size_t)BHN*SEQ*HD];
__device__ float g_v[(size_t)BHN*SEQ*HD];
__device__ float g_ao[(size_t)BATCH*SEQ*CDIM];
__device__ float g_xr[(size_t)BATCH*SEQ*CDIM];     // x, tf32, col k-perm
__device__ float g_wqr[(size_t)3*CDIM*CDIM];       // qkv_w, tf32, col k-perm, q/k rows perm
__device__ float g_wpr[(size_t)CDIM*CDIM];         // proj_w, tf32, col k-perm
__device__ float g_bqkv[3*CDIM];                   // qkv_b, q/k sections row-perm

__device__ __forceinline__ unsigned f2tf32(float f) {
    unsigned u;
    asm("cvt.rna.tf32.f32 %0, %1;" : "=r"(u) : "f"(f));
    return u;
}
__device__ __forceinline__ uint32_t smem_u32(const void* p) {
    uint32_t a;
    asm("{ .reg .u64 t; cvta.to.shared.u64 t, %1; cvt.u32.u64 %0, t; }"
        : "=r"(a) : "l"(p));
    return a;
}
__device__ __forceinline__ void cp16(uint32_t dst, const void* src) {
    asm volatile("cp.async.cg.shared.global [%0], [%1], 16;"
                 :: "r"(dst), "l"(__cvta_generic_to_global(src)) : "memory");
}
__device__ __forceinline__ void cp_commit() {
    asm volatile("cp.async.commit_group;" ::: "memory");
}
template<int N>
__device__ __forceinline__ void cp_wait() {
    asm volatile("cp.async.wait_group %0;" :: "n"(N) : "memory");
}
__device__ __forceinline__ void mma_tf32(float c[4], const unsigned a[4],
                                         unsigned b0, unsigned b1) {
    asm volatile(
        "mma.sync.aligned.m16n8k8.row.col.f32.tf32.tf32.f32 "
        "{%0,%1,%2,%3}, {%4,%5,%6,%7}, {%8,%9}, {%0,%1,%2,%3};\n"
        : "+f"(c[0]), "+f"(c[1]), "+f"(c[2]), "+f"(c[3])
        : "r"(a[0]), "r"(a[1]), "r"(a[2]), "r"(a[3]), "r"(b0), "r"(b1));
}
// storage position j within an 8-group holds logical element invp(j)
__device__ __forceinline__ int invp(int j) { return ((j & 1) << 2) | (j >> 1); }

// ---------------------------------------------------------------------------
// Fused pre-round + permute for x, qkv_w, proj_w (8-col groups) + bias perm.
// ---------------------------------------------------------------------------
#define GX (BATCH*SEQ*CDIM/8)
#define GW (3*CDIM*CDIM/8)
#define GP (CDIM*CDIM/8)
__global__ void pre_all(const float* __restrict__ x, const float* __restrict__ qkv_w,
                        const float* __restrict__ proj_w, const float* __restrict__ qkv_b)
{
    int i = blockIdx.x * blockDim.x + threadIdx.x;
    if (i < GX + GW + GP) {
        const float* src;
        float* dst;
        int li, which;
        if (i < GX)            { src = x;      dst = g_xr;  li = i;            which = 0; }
        else if (i < GX + GW)  { src = qkv_w;  dst = g_wqr; li = i - GX;       which = 1; }
        else                   { src = proj_w; dst = g_wpr; li = i - GX - GW;  which = 2; }
        const int gpr = CDIM >> 3;
        const int row = li / gpr, cg = li - row * gpr;
        int srow = row;
        if (which == 1 && row < 2 * CDIM) srow = (row & ~7) | invp(row & 7);
        const float* s = src + (size_t)srow * CDIM + cg * 8;
        float4 f0 = *(const float4*)(s);
        float4 f1 = *(const float4*)(s + 4);
        uint4 u0, u1;
        u0.x = f2tf32(f0.x); u0.y = f2tf32(f1.x); u0.z = f2tf32(f0.y); u0.w = f2tf32(f1.y);
        u1.x = f2tf32(f0.z); u1.y = f2tf32(f1.z); u1.z = f2tf32(f0.w); u1.w = f2tf32(f1.w);
        uint4* d = (uint4*)(dst + (size_t)row * CDIM + cg * 8);
        d[0] = u0; d[1] = u1;
    } else {
        int j = i - (GX + GW + GP);
        if (j < 3 * CDIM) {
            int sj = (j < 2 * CDIM) ? ((j & ~7) | invp(j & 7)) : j;
            g_bqkv[j] = qkv_b[sj];
        }
    }
}

// ---------------------------------------------------------------------------
// Tensor-core GEMM (mma.sync tf32), cp.async 2-stage, ISSUE-BEFORE-WAIT (R9).
// BM=BN=128, BK=32, 8 warps (2x4), warp tile 64x32. Row stride 40 words.
// MODE 0: A=g_xr, W=g_wqr, bias=g_bqkv, scatter tf32-rounded q/k/v.
// MODE 1: A=g_ao, W=g_wpr, plain fp32 output.
// ---------------------------------------------------------------------------
template<int MODE>
__global__ __launch_bounds__(256, 2)
void gemm_tc(const float* __restrict__ biasp, float* __restrict__ Cout,
             int M, int N, int K)
{
    extern __shared__ unsigned gsm[];   // 2 stages * (5120 A + 5120 B)
    const uint32_t sb = smem_u32(gsm);

    const int tid  = threadIdx.x;
    const int lane = tid & 31, warp = tid >> 5;
    const int g    = lane >> 2, tig = lane & 3;
    const int wm   = (warp >> 2) * 64;
    const int wn   = (warp & 3) * 32;
    const int m0   = blockIdx.y * 128;
    const int n0   = blockIdx.x * 128;

    const float* Ag = ((MODE == 1) ? (const float*)g_ao : (const float*)g_xr)
                      + (size_t)m0 * K;
    const float* Wg = ((MODE == 1) ? (const float*)g_wpr : (const float*)g_wqr)
                      + (size_t)n0 * K;
    const float* bias = (MODE == 0) ? (const float*)g_bqkv : biasp;

    const int NT = K / 32;

    auto issue = [&](int t, int s) {
        const int kb = t * 32;
        const uint32_t abase = sb + (s * 10240) * 4;
        const uint32_t wbase = abase + 5120 * 4;
        #pragma unroll
        for (int j = 0; j < 4; j++) {
            const int idx = tid + 256 * j;
            const int r = idx >> 3, c = (idx & 7) << 2;
            cp16(abase + (r * 40 + c) * 4, Ag + (size_t)r * K + kb + c);
            cp16(wbase + (r * 40 + c) * 4, Wg + (size_t)r * K + kb + c);
        }
        cp_commit();
    };

    float acc[4][4][4];
    #pragma unroll
    for (int mi = 0; mi < 4; mi++)
        #pragma unroll
        for (int nj = 0; nj < 4; nj++)
            #pragma unroll
            for (int c = 0; c < 4; c++) acc[mi][nj][c] = 0.f;

    issue(0, 0);
    for (int t = 0; t < NT; t++) {
        const int s = t & 1;
        if (t + 1 < NT) issue(t + 1, s ^ 1);     // issue BEFORE wait: pipeline depth
        if (t + 1 < NT) cp_wait<1>(); else cp_wait<0>();
        __syncthreads();

        const unsigned* Asu = gsm + s * 10240;
        const unsigned* Wsu = Asu + 5120;
        #pragma unroll
        for (int ks = 0; ks < 4; ks++) {
            const int kc = 8 * ks + 2 * tig;
            uint2 bfr[4];
            #pragma unroll
            for (int nj = 0; nj < 4; nj++)
                bfr[nj] = *(const uint2*)&Wsu[(wn + 8*nj + g) * 40 + kc];
            #pragma unroll
            for (int mi = 0; mi < 4; mi++) {
                uint2 a01 = *(const uint2*)&Asu[(wm + 16*mi + g    ) * 40 + kc];
                uint2 a23 = *(const uint2*)&Asu[(wm + 16*mi + 8 + g) * 40 + kc];
                unsigned afr[4] = {a01.x, a23.x, a01.y, a23.y};
                #pragma unroll
                for (int nj = 0; nj < 4; nj++)
                    mma_tf32(acc[mi][nj], afr, bfr[nj].x, bfr[nj].y);
            }
        }
        __syncthreads();
    }

    float2 bv[4];
    int colv[4];
    #pragma unroll
    for (int nj = 0; nj < 4; nj++) {
        const int col = n0 + wn + 8*nj + 2*tig;
        colv[nj] = col;
        bv[nj].x = bias[col];
        bv[nj].y = bias[col + 1];
    }

    if (MODE == 0) {
        const int tsel = n0 / CDIM;
        float* dst = (tsel == 0) ? g_q : (tsel == 1) ? g_k : g_v;
        const int b = m0 >> 10;
        #pragma unroll
        for (int mi = 0; mi < 4; mi++) {
            #pragma unroll
            for (int rr = 0; rr < 2; rr++) {
                const int row = m0 + wm + 16*mi + g + 8*rr;
                const int n   = row & (SEQ - 1);
                #pragma unroll
                for (int nj = 0; nj < 4; nj++) {
                    const int rem = colv[nj] - tsel * CDIM;
                    const int h = rem >> 6;
                    const int d = rem & 63;
                    float2 v;
                    v.x = __uint_as_float(f2tf32(acc[mi][nj][2*rr + 0] + bv[nj].x));
                    v.y = __uint_as_float(f2tf32(acc[mi][nj][2*rr + 1] + bv[nj].y));
                    *(float2*)&dst[(((size_t)b * NHEADS + h) * SEQ + n) * HD + d] = v;
                }
            }
        }
    } else {
        #pragma unroll
        for (int mi = 0; mi < 4; mi++) {
            #pragma unroll
            for (int rr = 0; rr < 2; rr++) {
                const int row = m0 + wm + 16*mi + g + 8*rr;
                #pragma unroll
                for (int nj = 0; nj < 4; nj++) {
                    float2 v;
                    v.x = acc[mi][nj][2*rr + 0] + bv[nj].x;
                    v.y = acc[mi][nj][2*rr + 1] + bv[nj].y;
                    *(float2*)&Cout[(size_t)row * N + colv[nj]] = v;
                }
            }
        }
    }
}

// ---------------------------------------------------------------------------
// Fused flash attention (R9 structure: 256 threads, 8 warps, 128 Q-rows),
// at 2 CTAs/SM (smem 108 KB x2 = 216 KB <= 228 KB carveout, reg cap 128).
// SMEM words: QP[0,9216) | stage s at 9216+s*9216: K(4608) then V(4608).
// ---------------------------------------------------------------------------
#define NKT (SEQ/64)
__global__ __launch_bounds__(256, 2)
void attn_tc()
{
    extern __shared__ unsigned sm[];
    unsigned* QPs = sm;
    const uint32_t sb = smem_u32(sm);

    const int tid  = threadIdx.x;
    const int lane = tid & 31, warp = tid >> 5;
    const int g    = lane >> 2, tig = lane & 3;
    const int bh   = blockIdx.y;
    const int qt   = blockIdx.x;

    const int p0 = ((tig & 1) ? 4 : 0) + (tig >> 1);

    const float* qg = g_q + (size_t)bh * SEQ * HD + (size_t)qt * 128 * HD;
    const float* kg = g_k + (size_t)bh * SEQ * HD;
    const float* vg = g_v + (size_t)bh * SEQ * HD;

    auto issue_kv = [&](int kt, int s) {
        const float* kp = kg + (size_t)kt * 64 * HD;
        const float* vp = vg + (size_t)kt * 64 * HD;
        const uint32_t kb = sb + (9216 + s * 9216) * 4;
        const uint32_t vb = kb + 4608 * 4;
        #pragma unroll
        for (int j = 0; j < 4; j++) {
            const int idx = tid + 256 * j;
            const int r = idx >> 4, c = (idx & 15) << 2;
            cp16(kb + (r * 72 + c) * 4, kp + (size_t)r * HD + c);
            cp16(vb + (r * 72 + c) * 4, vp + (size_t)r * HD + c);
        }
        cp_commit();
    };

    #pragma unroll
    for (int j = 0; j < 8; j++) {
        const int idx = tid + 256 * j;
        const int r = idx >> 4, c = (idx & 15) << 2;
        cp16(sb + (r * 72 + c) * 4, qg + (size_t)r * HD + c);
    }
    cp_commit();
    issue_kv(0, 0);
    cp_wait<1>();
    __syncthreads();

    unsigned aq[8][4];
    {
        const int r = 16 * warp;
        #pragma unroll
        for (int ks = 0; ks < 8; ks++) {
            const int kc = 8*ks + 2*tig;
            uint2 q01 = *(const uint2*)&QPs[(r + g    ) * 72 + kc];
            uint2 q23 = *(const uint2*)&QPs[(r + 8 + g) * 72 + kc];
            aq[ks][0] = q01.x; aq[ks][1] = q23.x; aq[ks][2] = q01.y; aq[ks][3] = q23.y;
        }
    }
    __syncthreads();

    float o[8][4];
    #pragma unroll
    for (int nj = 0; nj < 8; nj++)
        #pragma unroll
        for (int c = 0; c < 4; c++) o[nj][c] = 0.f;
    float m0r = -1e30f, m1r = -1e30f, l0 = 0.f, l1 = 0.f;

    for (int kt = 0; kt < NKT; kt++) {
        const int s = kt & 1;
        if (kt + 1 < NKT) issue_kv(kt + 1, s ^ 1);   // issue before wait
        if (kt + 1 < NKT) cp_wait<1>(); else cp_wait<0>();
        __syncthreads();

        const unsigned* Ks = sm + 9216 + s * 9216;
        const unsigned* Vs = Ks + 4608;

        float sc[8][4];
        #pragma unroll
        for (int nj = 0; nj < 8; nj++)
            #pragma unroll
            for (int c = 0; c < 4; c++) sc[nj][c] = 0.f;

        #pragma unroll
        for (int ks = 0; ks < 8; ks++) {
            const int kc = 8*ks + 2*tig;
            #pragma unroll
            for (int nj = 0; nj < 8; nj++) {
                uint2 b = *(const uint2*)&Ks[(8*nj + g) * 72 + kc];
                mma_tf32(sc[nj], aq[ks], b.x, b.y);
            }
        }

        float rm0 = -1e30f, rm1 = -1e30f;
        #pragma unroll
        for (int nj = 0; nj < 8; nj++) {
            sc[nj][0] *= SCALEF; sc[nj][1] *= SCALEF;
            sc[nj][2] *= SCALEF; sc[nj][3] *= SCALEF;
            rm0 = fmaxf(rm0, fmaxf(sc[nj][0], sc[nj][1]));
            rm1 = fmaxf(rm1, fmaxf(sc[nj][2], sc[nj][3]));
        }
        rm0 = fmaxf(rm0, __shfl_xor_sync(0xffffffffu, rm0, 1));
        rm0 = fmaxf(rm0, __shfl_xor_sync(0xffffffffu, rm0, 2));
        rm1 = fmaxf(rm1, __shfl_xor_sync(0xffffffffu, rm1, 1));
        rm1 = fmaxf(rm1, __shfl_xor_sync(0xffffffffu, rm1, 2));

        const float mn0 = fmaxf(m0r, rm0);
        const float mn1 = fmaxf(m1r, rm1);
        const float cr0 = __expf(m0r - mn0);
        const float cr1 = __expf(m1r - mn1);
        float rs0 = 0.f, rs1 = 0.f;
        #pragma unroll
        for (int nj = 0; nj < 8; nj++) {
            sc[nj][0] = __expf(sc[nj][0] - mn0);
            sc[nj][1] = __expf(sc[nj][1] - mn0);
            sc[nj][2] = __expf(sc[nj][2] - mn1);
            sc[nj][3] = __expf(sc[nj][3] - mn1);
            rs0 += sc[nj][0] + sc[nj][1];
            rs1 += sc[nj][2] + sc[nj][3];
        }
        rs0 += __shfl_xor_sync(0xffffffffu, rs0, 1);
        rs0 += __shfl_xor_sync(0xffffffffu, rs0, 2);
        rs1 += __shfl_xor_sync(0xffffffffu, rs1, 1);
        rs1 += __shfl_xor_sync(0xffffffffu, rs1, 2);
        l0 = l0 * cr0 + rs0;  m0r = mn0;
        l1 = l1 * cr1 + rs1;  m1r = mn1;
        #pragma unroll
        for (int nj = 0; nj < 8; nj++) {
            o[nj][0] *= cr0; o[nj][1] *= cr0;
            o[nj][2] *= cr1; o[nj][3] *= cr1;
        }

        // stage P at permuted n-positions (warp-private rows)
        {
            const int r0 = 16*warp + g;
            #pragma unroll
            for (int nj = 0; nj < 8; nj++) {
                QPs[ r0      * 72 + 8*nj + p0    ] = f2tf32(sc[nj][0]);
                QPs[ r0      * 72 + 8*nj + p0 + 2] = f2tf32(sc[nj][1]);
                QPs[(r0 + 8) * 72 + 8*nj + p0    ] = f2tf32(sc[nj][2]);
                QPs[(r0 + 8) * 72 + 8*nj + p0 + 2] = f2tf32(sc[nj][3]);
            }
        }
        __syncwarp();

        #pragma unroll
        for (int ks = 0; ks < 8; ks++) {
            const int kc = 8*ks + 2*tig;
            uint2 p01 = *(const uint2*)&QPs[(16*warp + g    ) * 72 + kc];
            uint2 p23 = *(const uint2*)&QPs[(16*warp + 8 + g) * 72 + kc];
            unsigned pa[4] = {p01.x, p23.x, p01.y, p23.y};
            #pragma unroll
            for (int nj = 0; nj < 8; nj++) {
                const unsigned b0 = Vs[(8*ks + tig    ) * 72 + 8*nj + g];
                const unsigned b1 = Vs[(8*ks + tig + 4) * 72 + 8*nj + g];
                mma_tf32(o[nj], pa, b0, b1);
            }
        }
        __syncthreads();
    }

    // normalize + write g_ao at k-permuted positions (tf32-rounded, for proj)
    const int b = bh / NHEADS, h = bh % NHEADS;
    const float inv0 = 1.f / l0, inv1 = 1.f / l1;
    const int r0 = qt * 128 + 16*warp + g;
    float* ao0 = g_ao + ((size_t)b * SEQ + r0    ) * CDIM + h * HD;
    float* ao1 = g_ao + ((size_t)b * SEQ + r0 + 8) * CDIM + h * HD;
    #pragma unroll
    for (int nj = 0; nj < 8; nj++) {
        const int q0 = 8*nj + p0, q1 = 8*nj + p0 + 2;
        ao0[q0] = __uint_as_float(f2tf32(o[nj][0] * inv0));
        ao0[q1] = __uint_as_float(f2tf32(o[nj][1] * inv0));
        ao1[q0] = __uint_as_float(f2tf32(o[nj][2] * inv1));
        ao1[q1] = __uint_as_float(f2tf32(o[nj][3] * inv1));
    }
}

// ---------------------------------------------------------------------------
// Inputs (metadata order): x, qkv_w, qkv_b, proj_w, proj_b, H, W
// ---------------------------------------------------------------------------
extern "C" void kernel_launch(void* const* d_in, const int* in_sizes, int n_in,
                              void* d_out, int out_size)
{
    (void)in_sizes; (void)n_in; (void)out_size;
    const float* x      = (const float*)d_in[0];
    const float* qkv_w  = (const float*)d_in[1];
    const float* qkv_b  = (const float*)d_in[2];
    const float* proj_w = (const float*)d_in[3];
    const float* proj_b = (const float*)d_in[4];
    float* out = (float*)d_out;

    const int smem_gemm = 2 * 10240 * (int)sizeof(unsigned);          // 81920 B
    const int smem_attn = (9216 + 2 * 9216) * (int)sizeof(unsigned);  // 110592 B
    cudaFuncSetAttribute(gemm_tc<0>, cudaFuncAttributeMaxDynamicSharedMemorySize, smem_gemm);
    cudaFuncSetAttribute(gemm_tc<1>, cudaFuncAttributeMaxDynamicSharedMemorySize, smem_gemm);
    cudaFuncSetAttribute(attn_tc,    cudaFuncAttributeMaxDynamicSharedMemorySize, smem_attn);

    // 0) fused pre-round + permute (x, qkv_w, proj_w, bias) in one launch
    {
        const int ntot = GX + GW + GP + 3 * CDIM;
        pre_all<<<(ntot + 255) / 256, 256>>>(x, qkv_w, proj_w, qkv_b);
    }

    // 1) QKV GEMM + bias -> per-head q/k/v (q/k d-permuted via W-row perm)
    gemm_tc<0><<<dim3(3 * CDIM / 128, (BATCH * SEQ) / 128), 256, smem_gemm>>>(
        nullptr, nullptr, BATCH * SEQ, 3 * CDIM, CDIM);

    // 2) fused flash attention -> g_ao (k-permuted, tf32-rounded)
    attn_tc<<<dim3(SEQ / 128, BHN), 256, smem_attn>>>();

    // 3) proj GEMM + bias -> d_out (fp32, natural layout)
    gemm_tc<1><<<dim3(CDIM / 128, (BATCH * SEQ) / 128), 256, smem_gemm>>>(
        proj_b, out, BATCH * SEQ, CDIM, CDIM);
}

// round 16
// speedup vs baseline: 1.5672x; 1.0205x over previous
#include <cuda_runtime.h>
#include <math.h>
#include <stdint.h>

#define SEQ    1024
#define CDIM   768
#define BATCH  8
#define NHEADS 12
#define HD     64
#define BHN    (BATCH*NHEADS)

// Scratch. q/k in [B,H,N,hd] hd-permuted; q pre-scaled by 0.125; v natural; ao k-permuted.
__device__ float g_q[(size_t)BHN*SEQ*HD];
__device__ float g_k[(size_t)BHN*SEQ*HD];
__device__ float g_v[(size_t)BHN*SEQ*HD];
__device__ float g_ao[(size_t)BATCH*SEQ*CDIM];
__device__ float g_xr[(size_t)BATCH*SEQ*CDIM];     // x, tf32, col k-perm
__device__ float g_wqr[(size_t)3*CDIM*CDIM];       // qkv_w, tf32, col k-perm, q/k rows perm
__device__ float g_wpr[(size_t)CDIM*CDIM];         // proj_w, tf32, col k-perm
__device__ float g_bqkv[3*CDIM];                   // qkv_b, q/k sections row-perm

__device__ __forceinline__ unsigned f2tf32(float f) {
    unsigned u;
    asm("cvt.rna.tf32.f32 %0, %1;" : "=r"(u) : "f"(f));
    return u;
}
__device__ __forceinline__ uint32_t smem_u32(const void* p) {
    uint32_t a;
    asm("{ .reg .u64 t; cvta.to.shared.u64 t, %1; cvt.u32.u64 %0, t; }"
        : "=r"(a) : "l"(p));
    return a;
}
__device__ __forceinline__ void cp16(uint32_t dst, const void* src) {
    asm volatile("cp.async.cg.shared.global [%0], [%1], 16;"
                 :: "r"(dst), "l"(__cvta_generic_to_global(src)) : "memory");
}
__device__ __forceinline__ void cp_commit() {
    asm volatile("cp.async.commit_group;" ::: "memory");
}
template<int N>
__device__ __forceinline__ void cp_wait() {
    asm volatile("cp.async.wait_group %0;" :: "n"(N) : "memory");
}
__device__ __forceinline__ void mma_tf32(float c[4], const unsigned a[4],
                                         unsigned b0, unsigned b1) {
    asm volatile(
        "mma.sync.aligned.m16n8k8.row.col.f32.tf32.tf32.f32 "
        "{%0,%1,%2,%3}, {%4,%5,%6,%7}, {%8,%9}, {%0,%1,%2,%3};\n"
        : "+f"(c[0]), "+f"(c[1]), "+f"(c[2]), "+f"(c[3])
        : "r"(a[0]), "r"(a[1]), "r"(a[2]), "r"(a[3]), "r"(b0), "r"(b1));
}
// storage position j within an 8-group holds logical element invp(j)
__device__ __forceinline__ int invp(int j) { return ((j & 1) << 2) | (j >> 1); }

// ---------------------------------------------------------------------------
// Fused pre-round + permute for x, qkv_w, proj_w (8-col groups) + bias perm.
// ---------------------------------------------------------------------------
#define GX (BATCH*SEQ*CDIM/8)
#define GW (3*CDIM*CDIM/8)
#define GP (CDIM*CDIM/8)
__global__ void pre_all(const float* __restrict__ x, const float* __restrict__ qkv_w,
                        const float* __restrict__ proj_w, const float* __restrict__ qkv_b)
{
    int i = blockIdx.x * blockDim.x + threadIdx.x;
    if (i < GX + GW + GP) {
        const float* src;
        float* dst;
        int li, which;
        if (i < GX)            { src = x;      dst = g_xr;  li = i;            which = 0; }
        else if (i < GX + GW)  { src = qkv_w;  dst = g_wqr; li = i - GX;       which = 1; }
        else                   { src = proj_w; dst = g_wpr; li = i - GX - GW;  which = 2; }
        const int gpr = CDIM >> 3;
        const int row = li / gpr, cg = li - row * gpr;
        int srow = row;
        if (which == 1 && row < 2 * CDIM) srow = (row & ~7) | invp(row & 7);
        const float* s = src + (size_t)srow * CDIM + cg * 8;
        float4 f0 = *(const float4*)(s);
        float4 f1 = *(const float4*)(s + 4);
        uint4 u0, u1;
        u0.x = f2tf32(f0.x); u0.y = f2tf32(f1.x); u0.z = f2tf32(f0.y); u0.w = f2tf32(f1.y);
        u1.x = f2tf32(f0.z); u1.y = f2tf32(f1.z); u1.z = f2tf32(f0.w); u1.w = f2tf32(f1.w);
        uint4* d = (uint4*)(dst + (size_t)row * CDIM + cg * 8);
        d[0] = u0; d[1] = u1;
    } else {
        int j = i - (GX + GW + GP);
        if (j < 3 * CDIM) {
            int sj = (j < 2 * CDIM) ? ((j & ~7) | invp(j & 7)) : j;
            g_bqkv[j] = qkv_b[sj];
        }
    }
}

// ---------------------------------------------------------------------------
// Tensor-core GEMM (mma.sync tf32), cp.async 2-stage, issue-before-wait.
// BM = MTILES*32 (two warp-rows of MTILES m16 tiles), BN=128, BK=32, 8 warps.
// Row stride 40 words (LDS.64 conflict-free per half-warp phase).
// MODE 0 (MTILES=4): A=g_xr, W=g_wqr, bias=g_bqkv, scatter q/k/v;
//                    q section pre-scaled by 0.125 (exact, power of 2).
// MODE 1 (MTILES=2): A=g_ao, W=g_wpr, plain fp32 output (BM=64: wave-friendly).
// ---------------------------------------------------------------------------
template<int MODE, int MTILES>
__global__ __launch_bounds__(256, 2)
void gemm_tc(const float* __restrict__ biasp, float* __restrict__ Cout,
             int M, int N, int K)
{
    const int BM     = MTILES * 32;
    const int AWORDS = BM * 40;
    const int STAGEW = AWORDS + 5120;        // + B 128*40

    extern __shared__ unsigned gsm[];
    const uint32_t sb = smem_u32(gsm);

    const int tid  = threadIdx.x;
    const int lane = tid & 31, warp = tid >> 5;
    const int g    = lane >> 2, tig = lane & 3;
    const int wm   = (warp >> 2) * (MTILES * 16);
    const int wn   = (warp & 3) * 32;
    const int m0   = blockIdx.y * BM;
    const int n0   = blockIdx.x * 128;

    const float* Ag = ((MODE == 1) ? (const float*)g_ao : (const float*)g_xr)
                      + (size_t)m0 * K;
    const float* Wg = ((MODE == 1) ? (const float*)g_wpr : (const float*)g_wqr)
                      + (size_t)n0 * K;
    const float* bias = (MODE == 0) ? (const float*)g_bqkv : biasp;

    const int NT = K / 32;

    auto issue = [&](int t, int s) {
        const int kb = t * 32;
        const uint32_t abase = sb + (s * STAGEW) * 4;
        const uint32_t wbase = abase + AWORDS * 4;
        #pragma unroll
        for (int j = 0; j < MTILES; j++) {           // A: BM*8 chunks
            const int idx = tid + 256 * j;
            const int r = idx >> 3, c = (idx & 7) << 2;
            cp16(abase + (r * 40 + c) * 4, Ag + (size_t)r * K + kb + c);
        }
        #pragma unroll
        for (int j = 0; j < 4; j++) {                // B: 1024 chunks
            const int idx = tid + 256 * j;
            const int r = idx >> 3, c = (idx & 7) << 2;
            cp16(wbase + (r * 40 + c) * 4, Wg + (size_t)r * K + kb + c);
        }
        cp_commit();
    };

    float acc[MTILES][4][4];
    #pragma unroll
    for (int mi = 0; mi < MTILES; mi++)
        #pragma unroll
        for (int nj = 0; nj < 4; nj++)
            #pragma unroll
            for (int c = 0; c < 4; c++) acc[mi][nj][c] = 0.f;

    issue(0, 0);
    for (int t = 0; t < NT; t++) {
        const int s = t & 1;
        if (t + 1 < NT) issue(t + 1, s ^ 1);     // issue BEFORE wait: pipeline depth
        if (t + 1 < NT) cp_wait<1>(); else cp_wait<0>();
        __syncthreads();

        const unsigned* Asu = gsm + s * STAGEW;
        const unsigned* Wsu = Asu + AWORDS;
        #pragma unroll
        for (int ks = 0; ks < 4; ks++) {
            const int kc = 8 * ks + 2 * tig;
            uint2 bfr[4];
            #pragma unroll
            for (int nj = 0; nj < 4; nj++)
                bfr[nj] = *(const uint2*)&Wsu[(wn + 8*nj + g) * 40 + kc];
            #pragma unroll
            for (int mi = 0; mi < MTILES; mi++) {
                uint2 a01 = *(const uint2*)&Asu[(wm + 16*mi + g    ) * 40 + kc];
                uint2 a23 = *(const uint2*)&Asu[(wm + 16*mi + 8 + g) * 40 + kc];
                unsigned afr[4] = {a01.x, a23.x, a01.y, a23.y};
                #pragma unroll
                for (int nj = 0; nj < 4; nj++)
                    mma_tf32(acc[mi][nj], afr, bfr[nj].x, bfr[nj].y);
            }
        }
        __syncthreads();
    }

    float2 bv[4];
    int colv[4];
    #pragma unroll
    for (int nj = 0; nj < 4; nj++) {
        const int col = n0 + wn + 8*nj + 2*tig;
        colv[nj] = col;
        bv[nj].x = bias[col];
        bv[nj].y = bias[col + 1];
    }

    if (MODE == 0) {
        const int tsel = n0 / CDIM;
        float* dst = (tsel == 0) ? g_q : (tsel == 1) ? g_k : g_v;
        const float qs = (tsel == 0) ? 0.125f : 1.0f;   // fold attention scale into q (exact)
        const int b = m0 >> 10;
        #pragma unroll
        for (int mi = 0; mi < MTILES; mi++) {
            #pragma unroll
            for (int rr = 0; rr < 2; rr++) {
                const int row = m0 + wm + 16*mi + g + 8*rr;
                const int n   = row & (SEQ - 1);
                #pragma unroll
                for (int nj = 0; nj < 4; nj++) {
                    const int rem = colv[nj] - tsel * CDIM;
                    const int h = rem >> 6;
                    const int d = rem & 63;
                    float2 v;
                    v.x = __uint_as_float(f2tf32((acc[mi][nj][2*rr + 0] + bv[nj].x) * qs));
                    v.y = __uint_as_float(f2tf32((acc[mi][nj][2*rr + 1] + bv[nj].y) * qs));
                    *(float2*)&dst[(((size_t)b * NHEADS + h) * SEQ + n) * HD + d] = v;
                }
            }
        }
    } else {
        #pragma unroll
        for (int mi = 0; mi < MTILES; mi++) {
            #pragma unroll
            for (int rr = 0; rr < 2; rr++) {
                const int row = m0 + wm + 16*mi + g + 8*rr;
                #pragma unroll
                for (int nj = 0; nj < 4; nj++) {
                    float2 v;
                    v.x = acc[mi][nj][2*rr + 0] + bv[nj].x;
                    v.y = acc[mi][nj][2*rr + 1] + bv[nj].y;
                    *(float2*)&Cout[(size_t)row * N + colv[nj]] = v;
                }
            }
        }
    }
}

// ---------------------------------------------------------------------------
// Fused flash attention (256 threads, 8 warps, 128 Q-rows, 2 CTAs/SM).
// q arrives pre-scaled by 0.125, so no scale multiply in the softmax path.
// SMEM words: QP[0,9216) | stage s at 9216+s*9216: K(4608) then V(4608).
// ---------------------------------------------------------------------------
#define NKT (SEQ/64)
__global__ __launch_bounds__(256, 2)
void attn_tc()
{
    extern __shared__ unsigned sm[];
    unsigned* QPs = sm;
    const uint32_t sb = smem_u32(sm);

    const int tid  = threadIdx.x;
    const int lane = tid & 31, warp = tid >> 5;
    const int g    = lane >> 2, tig = lane & 3;
    const int bh   = blockIdx.y;
    const int qt   = blockIdx.x;

    const int p0 = ((tig & 1) ? 4 : 0) + (tig >> 1);

    const float* qg = g_q + (size_t)bh * SEQ * HD + (size_t)qt * 128 * HD;
    const float* kg = g_k + (size_t)bh * SEQ * HD;
    const float* vg = g_v + (size_t)bh * SEQ * HD;

    auto issue_kv = [&](int kt, int s) {
        const float* kp = kg + (size_t)kt * 64 * HD;
        const float* vp = vg + (size_t)kt * 64 * HD;
        const uint32_t kb = sb + (9216 + s * 9216) * 4;
        const uint32_t vb = kb + 4608 * 4;
        #pragma unroll
        for (int j = 0; j < 4; j++) {
            const int idx = tid + 256 * j;
            const int r = idx >> 4, c = (idx & 15) << 2;
            cp16(kb + (r * 72 + c) * 4, kp + (size_t)r * HD + c);
            cp16(vb + (r * 72 + c) * 4, vp + (size_t)r * HD + c);
        }
        cp_commit();
    };

    #pragma unroll
    for (int j = 0; j < 8; j++) {
        const int idx = tid + 256 * j;
        const int r = idx >> 4, c = (idx & 15) << 2;
        cp16(sb + (r * 72 + c) * 4, qg + (size_t)r * HD + c);
    }
    cp_commit();
    issue_kv(0, 0);
    cp_wait<1>();
    __syncthreads();

    unsigned aq[8][4];
    {
        const int r = 16 * warp;
        #pragma unroll
        for (int ks = 0; ks < 8; ks++) {
            const int kc = 8*ks + 2*tig;
            uint2 q01 = *(const uint2*)&QPs[(r + g    ) * 72 + kc];
            uint2 q23 = *(const uint2*)&QPs[(r + 8 + g) * 72 + kc];
            aq[ks][0] = q01.x; aq[ks][1] = q23.x; aq[ks][2] = q01.y; aq[ks][3] = q23.y;
        }
    }
    __syncthreads();

    float o[8][4];
    #pragma unroll
    for (int nj = 0; nj < 8; nj++)
        #pragma unroll
        for (int c = 0; c < 4; c++) o[nj][c] = 0.f;
    float m0r = -1e30f, m1r = -1e30f, l0 = 0.f, l1 = 0.f;

    for (int kt = 0; kt < NKT; kt++) {
        const int s = kt & 1;
        if (kt + 1 < NKT) issue_kv(kt + 1, s ^ 1);   // issue before wait
        if (kt + 1 < NKT) cp_wait<1>(); else cp_wait<0>();
        __syncthreads();

        const unsigned* Ks = sm + 9216 + s * 9216;
        const unsigned* Vs = Ks + 4608;

        float sc[8][4];
        #pragma unroll
        for (int nj = 0; nj < 8; nj++)
            #pragma unroll
            for (int c = 0; c < 4; c++) sc[nj][c] = 0.f;

        #pragma unroll
        for (int ks = 0; ks < 8; ks++) {
            const int kc = 8*ks + 2*tig;
            #pragma unroll
            for (int nj = 0; nj < 8; nj++) {
                uint2 b = *(const uint2*)&Ks[(8*nj + g) * 72 + kc];
                mma_tf32(sc[nj], aq[ks], b.x, b.y);
            }
        }

        // online softmax (scores already scaled: q pre-multiplied by 0.125)
        float rm0 = -1e30f, rm1 = -1e30f;
        #pragma unroll
        for (int nj = 0; nj < 8; nj++) {
            rm0 = fmaxf(rm0, fmaxf(sc[nj][0], sc[nj][1]));
            rm1 = fmaxf(rm1, fmaxf(sc[nj][2], sc[nj][3]));
        }
        rm0 = fmaxf(rm0, __shfl_xor_sync(0xffffffffu, rm0, 1));
        rm0 = fmaxf(rm0, __shfl_xor_sync(0xffffffffu, rm0, 2));
        rm1 = fmaxf(rm1, __shfl_xor_sync(0xffffffffu, rm1, 1));
        rm1 = fmaxf(rm1, __shfl_xor_sync(0xffffffffu, rm1, 2));

        const float mn0 = fmaxf(m0r, rm0);
        const float mn1 = fmaxf(m1r, rm1);
        const float cr0 = __expf(m0r - mn0);
        const float cr1 = __expf(m1r - mn1);
        float rs0 = 0.f, rs1 = 0.f;
        #pragma unroll
        for (int nj = 0; nj < 8; nj++) {
            sc[nj][0] = __expf(sc[nj][0] - mn0);
            sc[nj][1] = __expf(sc[nj][1] - mn0);
            sc[nj][2] = __expf(sc[nj][2] - mn1);
            sc[nj][3] = __expf(sc[nj][3] - mn1);
            rs0 += sc[nj][0] + sc[nj][1];
            rs1 += sc[nj][2] + sc[nj][3];
        }
        rs0 += __shfl_xor_sync(0xffffffffu, rs0, 1);
        rs0 += __shfl_xor_sync(0xffffffffu, rs0, 2);
        rs1 += __shfl_xor_sync(0xffffffffu, rs1, 1);
        rs1 += __shfl_xor_sync(0xffffffffu, rs1, 2);
        l0 = l0 * cr0 + rs0;  m0r = mn0;
        l1 = l1 * cr1 + rs1;  m1r = mn1;
        #pragma unroll
        for (int nj = 0; nj < 8; nj++) {
            o[nj][0] *= cr0; o[nj][1] *= cr0;
            o[nj][2] *= cr1; o[nj][3] *= cr1;
        }

        // stage P at permuted n-positions (warp-private rows)
        {
            const int r0 = 16*warp + g;
            #pragma unroll
            for (int nj = 0; nj < 8; nj++) {
                QPs[ r0      * 72 + 8*nj + p0    ] = f2tf32(sc[nj][0]);
                QPs[ r0      * 72 + 8*nj + p0 + 2] = f2tf32(sc[nj][1]);
                QPs[(r0 + 8) * 72 + 8*nj + p0    ] = f2tf32(sc[nj][2]);
                QPs[(r0 + 8) * 72 + 8*nj + p0 + 2] = f2tf32(sc[nj][3]);
            }
        }
        __syncwarp();

        #pragma unroll
        for (int ks = 0; ks < 8; ks++) {
            const int kc = 8*ks + 2*tig;
            uint2 p01 = *(const uint2*)&QPs[(16*warp + g    ) * 72 + kc];
            uint2 p23 = *(const uint2*)&QPs[(16*warp + 8 + g) * 72 + kc];
            unsigned pa[4] = {p01.x, p23.x, p01.y, p23.y};
            #pragma unroll
            for (int nj = 0; nj < 8; nj++) {
                const unsigned b0 = Vs[(8*ks + tig    ) * 72 + 8*nj + g];
                const unsigned b1 = Vs[(8*ks + tig + 4) * 72 + 8*nj + g];
                mma_tf32(o[nj], pa, b0, b1);
            }
        }
        __syncthreads();
    }

    // normalize + write g_ao at k-permuted positions (tf32-rounded, for proj)
    const int b = bh / NHEADS, h = bh % NHEADS;
    const float inv0 = 1.f / l0, inv1 = 1.f / l1;
    const int r0 = qt * 128 + 16*warp + g;
    float* ao0 = g_ao + ((size_t)b * SEQ + r0    ) * CDIM + h * HD;
    float* ao1 = g_ao + ((size_t)b * SEQ + r0 + 8) * CDIM + h * HD;
    #pragma unroll
    for (int nj = 0; nj < 8; nj++) {
        const int q0 = 8*nj + p0, q1 = 8*nj + p0 + 2;
        ao0[q0] = __uint_as_float(f2tf32(o[nj][0] * inv0));
        ao0[q1] = __uint_as_float(f2tf32(o[nj][1] * inv0));
        ao1[q0] = __uint_as_float(f2tf32(o[nj][2] * inv1));
        ao1[q1] = __uint_as_float(f2tf32(o[nj][3] * inv1));
    }
}

// ---------------------------------------------------------------------------
// Inputs (metadata order): x, qkv_w, qkv_b, proj_w, proj_b, H, W
// ---------------------------------------------------------------------------
extern "C" void kernel_launch(void* const* d_in, const int* in_sizes, int n_in,
                              void* d_out, int out_size)
{
    (void)in_sizes; (void)n_in; (void)out_size;
    const float* x      = (const float*)d_in[0];
    const float* qkv_w  = (const float*)d_in[1];
    const float* qkv_b  = (const float*)d_in[2];
    const float* proj_w = (const float*)d_in[3];
    const float* proj_b = (const float*)d_in[4];
    float* out = (float*)d_out;

    const int smem_qkv  = 2 * 10240 * (int)sizeof(unsigned);          // 81920 B (BM=128)
    const int smem_proj = 2 * 7680  * (int)sizeof(unsigned);          // 61440 B (BM=64)
    const int smem_attn = (9216 + 2 * 9216) * (int)sizeof(unsigned);  // 110592 B
    cudaFuncSetAttribute((const void*)gemm_tc<0,4>, cudaFuncAttributeMaxDynamicSharedMemorySize, smem_qkv);
    cudaFuncSetAttribute((const void*)gemm_tc<1,2>, cudaFuncAttributeMaxDynamicSharedMemorySize, smem_proj);
    cudaFuncSetAttribute((const void*)attn_tc,      cudaFuncAttributeMaxDynamicSharedMemorySize, smem_attn);

    // 0) fused pre-round + permute (x, qkv_w, proj_w, bias) in one launch
    {
        const int ntot = GX + GW + GP + 3 * CDIM;
        pre_all<<<(ntot + 255) / 256, 256>>>(x, qkv_w, proj_w, qkv_b);
    }

    // 1) QKV GEMM + bias -> per-head q/k/v (q pre-scaled by 0.125)
    gemm_tc<0,4><<<dim3(3 * CDIM / 128, (BATCH * SEQ) / 128), 256, smem_qkv>>>(
        nullptr, nullptr, BATCH * SEQ, 3 * CDIM, CDIM);

    // 2) fused flash attention -> g_ao (k-permuted, tf32-rounded)
    attn_tc<<<dim3(SEQ / 128, BHN), 256, smem_attn>>>();

    // 3) proj GEMM + bias -> d_out (BM=64: 768 CTAs, better wave fill)
    gemm_tc<1,2><<<dim3(CDIM / 128, (BATCH * SEQ) / 64), 256, smem_proj>>>(
        proj_b, out, BATCH * SEQ, CDIM, CDIM);
}

// round 17
// speedup vs baseline: 2.0949x; 1.3367x over previous
#include <cuda_runtime.h>
#include <cuda_fp16.h>
#include <math.h>
#include <stdint.h>

#define SEQ    1024
#define CDIM   768
#define BATCH  8
#define NHEADS 12
#define HD     64
#define BHN    (BATCH*NHEADS)

// Scratch. q/k fp32 tf32-rounded, hd-permuted (8-group); q pre-scaled 0.125; v natural.
// ao is fp16, col-permuted in fp16 16-groups (A-operand of proj).
__device__ float  g_q[(size_t)BHN*SEQ*HD];
__device__ float  g_k[(size_t)BHN*SEQ*HD];
__device__ float  g_v[(size_t)BHN*SEQ*HD];
__device__ __half g_ao[(size_t)BATCH*SEQ*CDIM];
__device__ __half g_xr[(size_t)BATCH*SEQ*CDIM];     // x, fp16, 16-group col perm
__device__ __half g_wqr[(size_t)3*CDIM*CDIM];       // qkv_w, fp16, col perm; q/k rows 8-perm
__device__ __half g_wpr[(size_t)CDIM*CDIM];         // proj_w, fp16, col perm
__device__ float  g_bqkv[3*CDIM];                   // qkv_b, q/k sections row-perm

__device__ __forceinline__ unsigned f2tf32(float f) {
    unsigned u;
    asm("cvt.rna.tf32.f32 %0, %1;" : "=r"(u) : "f"(f));
    return u;
}
__device__ __forceinline__ uint32_t smem_u32(const void* p) {
    uint32_t a;
    asm("{ .reg .u64 t; cvta.to.shared.u64 t, %1; cvt.u32.u64 %0, t; }"
        : "=r"(a) : "l"(p));
    return a;
}
__device__ __forceinline__ void cp16(uint32_t dst, const void* src) {
    asm volatile("cp.async.cg.shared.global [%0], [%1], 16;"
                 :: "r"(dst), "l"(__cvta_generic_to_global(src)) : "memory");
}
__device__ __forceinline__ void cp_commit() {
    asm volatile("cp.async.commit_group;" ::: "memory");
}
template<int N>
__device__ __forceinline__ void cp_wait() {
    asm volatile("cp.async.wait_group %0;" :: "n"(N) : "memory");
}
// tf32 m16n8k8 (attention only)
__device__ __forceinline__ void mma_tf32(float c[4], const unsigned a[4],
                                         unsigned b0, unsigned b1) {
    asm volatile(
        "mma.sync.aligned.m16n8k8.row.col.f32.tf32.tf32.f32 "
        "{%0,%1,%2,%3}, {%4,%5,%6,%7}, {%8,%9}, {%0,%1,%2,%3};\n"
        : "+f"(c[0]), "+f"(c[1]), "+f"(c[2]), "+f"(c[3])
        : "r"(a[0]), "r"(a[1]), "r"(a[2]), "r"(a[3]), "r"(b0), "r"(b1));
}
// fp16 m16n8k16 (GEMMs)
__device__ __forceinline__ void mma_f16(float c[4], unsigned a0, unsigned a1,
                                        unsigned a2, unsigned a3,
                                        unsigned b0, unsigned b1) {
    asm volatile(
        "mma.sync.aligned.m16n8k16.row.col.f32.f16.f16.f32 "
        "{%0,%1,%2,%3}, {%4,%5,%6,%7}, {%8,%9}, {%0,%1,%2,%3};\n"
        : "+f"(c[0]), "+f"(c[1]), "+f"(c[2]), "+f"(c[3])
        : "r"(a0), "r"(a1), "r"(a2), "r"(a3), "r"(b0), "r"(b1));
}
// 8-group inverse perm (q/k row storage, unchanged from tf32 rounds)
__device__ __forceinline__ int invp(int j) { return ((j & 1) << 2) | (j >> 1); }

// ---------------------------------------------------------------------------
// Pre-round to fp16 + 16-group k-interleave: stored[4j..4j+3] = {2j,2j+1,2j+8,2j+9}.
// which 1 additionally applies the OLD 8-group row perm to q/k weight rows.
// ---------------------------------------------------------------------------
#define GX16 (BATCH*SEQ*CDIM/16)
#define GW16 (3*CDIM*CDIM/16)
#define GP16 (CDIM*CDIM/16)
__global__ void pre_all(const float* __restrict__ x, const float* __restrict__ qkv_w,
                        const float* __restrict__ proj_w, const float* __restrict__ qkv_b)
{
    int i = blockIdx.x * blockDim.x + threadIdx.x;
    if (i < GX16 + GW16 + GP16) {
        const float* src;
        __half* dst;
        int li, which;
        if (i < GX16)              { src = x;      dst = g_xr;  li = i;               which = 0; }
        else if (i < GX16 + GW16)  { src = qkv_w;  dst = g_wqr; li = i - GX16;        which = 1; }
        else                       { src = proj_w; dst = g_wpr; li = i - GX16 - GW16; which = 2; }
        const int gpr = CDIM >> 4;
        const int row = li / gpr, cg = li - row * gpr;
        int srow = row;
        if (which == 1 && row < 2 * CDIM) srow = (row & ~7) | invp(row & 7);
        const float* s = src + (size_t)srow * CDIM + cg * 16;
        float f[16];
        #pragma unroll
        for (int u = 0; u < 4; u++) {
            float4 t4 = *(const float4*)(s + 4*u);
            f[4*u] = t4.x; f[4*u+1] = t4.y; f[4*u+2] = t4.z; f[4*u+3] = t4.w;
        }
        __half2 hp[8];
        #pragma unroll
        for (int j = 0; j < 4; j++) {
            hp[2*j    ] = __floats2half2_rn(f[2*j],     f[2*j + 1]);
            hp[2*j + 1] = __floats2half2_rn(f[2*j + 8], f[2*j + 9]);
        }
        uint4* d = (uint4*)(dst + (size_t)row * CDIM + cg * 16);
        d[0] = ((const uint4*)hp)[0];
        d[1] = ((const uint4*)hp)[1];
    } else {
        int j = i - (GX16 + GW16 + GP16);
        if (j < 3 * CDIM) {
            int sj = (j < 2 * CDIM) ? ((j & ~7) | invp(j & 7)) : j;
            g_bqkv[j] = qkv_b[sj];
        }
    }
}

// ---------------------------------------------------------------------------
// fp16 tensor-core GEMM: C = A @ W^T + bias. BM=MTILES*32, BN=128, BK=64,
// 8 warps (2 x 4), warp tile (MTILES*16) x 32. Row stride 80 halves (40 words):
// per-phase banks 40g+2t mod 32 cover all 32 banks -> conflict-free LDS.64.
// cp.async 2-stage, issue-before-wait. MODE 0: scatter q/k/v (tf32-rounded
// fp32, q scaled 0.125). MODE 1: A=g_ao (fp16 perm), fp32 out.
// ---------------------------------------------------------------------------
template<int MODE, int MTILES>
__global__ __launch_bounds__(256, 2)
void gemm_tc(const float* __restrict__ biasp, float* __restrict__ Cout,
             int M, int N, int K)
{
    const int BM     = MTILES * 32;
    const int AWORDS = BM * 40;          // A stage words (uint32)
    const int STAGEW = AWORDS + 5120;    // + B 128*40

    extern __shared__ unsigned gsm[];
    const uint32_t sb = smem_u32(gsm);

    const int tid  = threadIdx.x;
    const int lane = tid & 31, warp = tid >> 5;
    const int g    = lane >> 2, tig = lane & 3;
    const int wm   = (warp >> 2) * (MTILES * 16);
    const int wn   = (warp & 3) * 32;
    const int m0   = blockIdx.y * BM;
    const int n0   = blockIdx.x * 128;

    const __half* Ag = ((MODE == 1) ? (const __half*)g_ao : (const __half*)g_xr)
                       + (size_t)m0 * K;
    const __half* Wg = ((MODE == 1) ? (const __half*)g_wpr : (const __half*)g_wqr)
                       + (size_t)n0 * K;
    const float* bias = (MODE == 0) ? (const float*)g_bqkv : biasp;

    const int NT = K / 64;   // 12 tiles

    auto issue = [&](int t, int s) {
        const int kb = t * 64;                       // halves
        const uint32_t abase = sb + (s * STAGEW) * 4;
        const uint32_t wbase = abase + AWORDS * 4;
        #pragma unroll
        for (int j = 0; j < MTILES; j++) {           // A: BM rows x 8 chunks
            const int idx = tid + 256 * j;
            const int r = idx >> 3, c = idx & 7;
            cp16(abase + r * 160 + c * 16, Ag + (size_t)r * K + kb + c * 8);
        }
        #pragma unroll
        for (int j = 0; j < 4; j++) {                // B: 128 rows x 8 chunks
            const int idx = tid + 256 * j;
            const int r = idx >> 3, c = idx & 7;
            cp16(wbase + r * 160 + c * 16, Wg + (size_t)r * K + kb + c * 8);
        }
        cp_commit();
    };

    float acc[MTILES][4][4];
    #pragma unroll
    for (int mi = 0; mi < MTILES; mi++)
        #pragma unroll
        for (int nj = 0; nj < 4; nj++)
            #pragma unroll
            for (int c = 0; c < 4; c++) acc[mi][nj][c] = 0.f;

    issue(0, 0);
    for (int t = 0; t < NT; t++) {
        const int s = t & 1;
        if (t + 1 < NT) issue(t + 1, s ^ 1);     // issue BEFORE wait
        if (t + 1 < NT) cp_wait<1>(); else cp_wait<0>();
        __syncthreads();

        const unsigned* Asu = gsm + s * STAGEW;
        const unsigned* Wsu = Asu + AWORDS;
        #pragma unroll
        for (int ks = 0; ks < 4; ks++) {
            const int off = ks * 8 + 2 * tig;    // word offset within row
            uint2 bfr[4];
            #pragma unroll
            for (int nj = 0; nj < 4; nj++)
                bfr[nj] = *(const uint2*)&Wsu[(wn + 8*nj + g) * 40 + off];
            #pragma unroll
            for (int mi = 0; mi < MTILES; mi++) {
                uint2 lo = *(const uint2*)&Asu[(wm + 16*mi + g    ) * 40 + off];
                uint2 hi = *(const uint2*)&Asu[(wm + 16*mi + 8 + g) * 40 + off];
                #pragma unroll
                for (int nj = 0; nj < 4; nj++)
                    mma_f16(acc[mi][nj], lo.x, hi.x, lo.y, hi.y,
                            bfr[nj].x, bfr[nj].y);
            }
        }
        __syncthreads();
    }

    float2 bv[4];
    int colv[4];
    #pragma unroll
    for (int nj = 0; nj < 4; nj++) {
        const int col = n0 + wn + 8*nj + 2*tig;
        colv[nj] = col;
        bv[nj].x = bias[col];
        bv[nj].y = bias[col + 1];
    }

    if (MODE == 0) {
        const int tsel = n0 / CDIM;
        float* dst = (tsel == 0) ? g_q : (tsel == 1) ? g_k : g_v;
        const float qs = (tsel == 0) ? 0.125f : 1.0f;   // fold attention scale (exact)
        const int b = m0 >> 10;
        #pragma unroll
        for (int mi = 0; mi < MTILES; mi++) {
            #pragma unroll
            for (int rr = 0; rr < 2; rr++) {
                const int row = m0 + wm + 16*mi + g + 8*rr;
                const int n   = row & (SEQ - 1);
                #pragma unroll
                for (int nj = 0; nj < 4; nj++) {
                    const int rem = colv[nj] - tsel * CDIM;
                    const int h = rem >> 6;
                    const int d = rem & 63;
                    float2 v;
                    v.x = __uint_as_float(f2tf32((acc[mi][nj][2*rr + 0] + bv[nj].x) * qs));
                    v.y = __uint_as_float(f2tf32((acc[mi][nj][2*rr + 1] + bv[nj].y) * qs));
                    *(float2*)&dst[(((size_t)b * NHEADS + h) * SEQ + n) * HD + d] = v;
                }
            }
        }
    } else {
        #pragma unroll
        for (int mi = 0; mi < MTILES; mi++) {
            #pragma unroll
            for (int rr = 0; rr < 2; rr++) {
                const int row = m0 + wm + 16*mi + g + 8*rr;
                #pragma unroll
                for (int nj = 0; nj < 4; nj++) {
                    float2 v;
                    v.x = acc[mi][nj][2*rr + 0] + bv[nj].x;
                    v.y = acc[mi][nj][2*rr + 1] + bv[nj].y;
                    *(float2*)&Cout[(size_t)row * N + colv[nj]] = v;
                }
            }
        }
    }
}

// ---------------------------------------------------------------------------
// Fused flash attention — tf32 path, UNCHANGED except the final write, which
// now emits fp16 at fp16-16-group permuted positions (proj A-operand layout).
// 256 threads, 8 warps, 128 Q-rows, 2 CTAs/SM. q pre-scaled by 0.125.
// ---------------------------------------------------------------------------
#define NKT (SEQ/64)
__global__ __launch_bounds__(256, 2)
void attn_tc()
{
    extern __shared__ unsigned sm[];
    unsigned* QPs = sm;
    const uint32_t sb = smem_u32(sm);

    const int tid  = threadIdx.x;
    const int lane = tid & 31, warp = tid >> 5;
    const int g    = lane >> 2, tig = lane & 3;
    const int bh   = blockIdx.y;
    const int qt   = blockIdx.x;

    const int p0 = ((tig & 1) ? 4 : 0) + (tig >> 1);

    const float* qg = g_q + (size_t)bh * SEQ * HD + (size_t)qt * 128 * HD;
    const float* kg = g_k + (size_t)bh * SEQ * HD;
    const float* vg = g_v + (size_t)bh * SEQ * HD;

    auto issue_kv = [&](int kt, int s) {
        const float* kp = kg + (size_t)kt * 64 * HD;
        const float* vp = vg + (size_t)kt * 64 * HD;
        const uint32_t kb = sb + (9216 + s * 9216) * 4;
        const uint32_t vb = kb + 4608 * 4;
        #pragma unroll
        for (int j = 0; j < 4; j++) {
            const int idx = tid + 256 * j;
            const int r = idx >> 4, c = (idx & 15) << 2;
            cp16(kb + (r * 72 + c) * 4, kp + (size_t)r * HD + c);
            cp16(vb + (r * 72 + c) * 4, vp + (size_t)r * HD + c);
        }
        cp_commit();
    };

    #pragma unroll
    for (int j = 0; j < 8; j++) {
        const int idx = tid + 256 * j;
        const int r = idx >> 4, c = (idx & 15) << 2;
        cp16(sb + (r * 72 + c) * 4, qg + (size_t)r * HD + c);
    }
    cp_commit();
    issue_kv(0, 0);
    cp_wait<1>();
    __syncthreads();

    unsigned aq[8][4];
    {
        const int r = 16 * warp;
        #pragma unroll
        for (int ks = 0; ks < 8; ks++) {
            const int kc = 8*ks + 2*tig;
            uint2 q01 = *(const uint2*)&QPs[(r + g    ) * 72 + kc];
            uint2 q23 = *(const uint2*)&QPs[(r + 8 + g) * 72 + kc];
            aq[ks][0] = q01.x; aq[ks][1] = q23.x; aq[ks][2] = q01.y; aq[ks][3] = q23.y;
        }
    }
    __syncthreads();

    float o[8][4];
    #pragma unroll
    for (int nj = 0; nj < 8; nj++)
        #pragma unroll
        for (int c = 0; c < 4; c++) o[nj][c] = 0.f;
    float m0r = -1e30f, m1r = -1e30f, l0 = 0.f, l1 = 0.f;

    for (int kt = 0; kt < NKT; kt++) {
        const int s = kt & 1;
        if (kt + 1 < NKT) issue_kv(kt + 1, s ^ 1);
        if (kt + 1 < NKT) cp_wait<1>(); else cp_wait<0>();
        __syncthreads();

        const unsigned* Ks = sm + 9216 + s * 9216;
        const unsigned* Vs = Ks + 4608;

        float sc[8][4];
        #pragma unroll
        for (int nj = 0; nj < 8; nj++)
            #pragma unroll
            for (int c = 0; c < 4; c++) sc[nj][c] = 0.f;

        #pragma unroll
        for (int ks = 0; ks < 8; ks++) {
            const int kc = 8*ks + 2*tig;
            #pragma unroll
            for (int nj = 0; nj < 8; nj++) {
                uint2 b = *(const uint2*)&Ks[(8*nj + g) * 72 + kc];
                mma_tf32(sc[nj], aq[ks], b.x, b.y);
            }
        }

        float rm0 = -1e30f, rm1 = -1e30f;
        #pragma unroll
        for (int nj = 0; nj < 8; nj++) {
            rm0 = fmaxf(rm0, fmaxf(sc[nj][0], sc[nj][1]));
            rm1 = fmaxf(rm1, fmaxf(sc[nj][2], sc[nj][3]));
        }
        rm0 = fmaxf(rm0, __shfl_xor_sync(0xffffffffu, rm0, 1));
        rm0 = fmaxf(rm0, __shfl_xor_sync(0xffffffffu, rm0, 2));
        rm1 = fmaxf(rm1, __shfl_xor_sync(0xffffffffu, rm1, 1));
        rm1 = fmaxf(rm1, __shfl_xor_sync(0xffffffffu, rm1, 2));

        const float mn0 = fmaxf(m0r, rm0);
        const float mn1 = fmaxf(m1r, rm1);
        const float cr0 = __expf(m0r - mn0);
        const float cr1 = __expf(m1r - mn1);
        float rs0 = 0.f, rs1 = 0.f;
        #pragma unroll
        for (int nj = 0; nj < 8; nj++) {
            sc[nj][0] = __expf(sc[nj][0] - mn0);
            sc[nj][1] = __expf(sc[nj][1] - mn0);
            sc[nj][2] = __expf(sc[nj][2] - mn1);
            sc[nj][3] = __expf(sc[nj][3] - mn1);
            rs0 += sc[nj][0] + sc[nj][1];
            rs1 += sc[nj][2] + sc[nj][3];
        }
        rs0 += __shfl_xor_sync(0xffffffffu, rs0, 1);
        rs0 += __shfl_xor_sync(0xffffffffu, rs0, 2);
        rs1 += __shfl_xor_sync(0xffffffffu, rs1, 1);
        rs1 += __shfl_xor_sync(0xffffffffu, rs1, 2);
        l0 = l0 * cr0 + rs0;  m0r = mn0;
        l1 = l1 * cr1 + rs1;  m1r = mn1;
        #pragma unroll
        for (int nj = 0; nj < 8; nj++) {
            o[nj][0] *= cr0; o[nj][1] *= cr0;
            o[nj][2] *= cr1; o[nj][3] *= cr1;
        }

        {
            const int r0 = 16*warp + g;
            #pragma unroll
            for (int nj = 0; nj < 8; nj++) {
                QPs[ r0      * 72 + 8*nj + p0    ] = f2tf32(sc[nj][0]);
                QPs[ r0      * 72 + 8*nj + p0 + 2] = f2tf32(sc[nj][1]);
                QPs[(r0 + 8) * 72 + 8*nj + p0    ] = f2tf32(sc[nj][2]);
                QPs[(r0 + 8) * 72 + 8*nj + p0 + 2] = f2tf32(sc[nj][3]);
            }
        }
        __syncwarp();

        #pragma unroll
        for (int ks = 0; ks < 8; ks++) {
            const int kc = 8*ks + 2*tig;
            uint2 p01 = *(const uint2*)&QPs[(16*warp + g    ) * 72 + kc];
            uint2 p23 = *(const uint2*)&QPs[(16*warp + 8 + g) * 72 + kc];
            unsigned pa[4] = {p01.x, p23.x, p01.y, p23.y};
            #pragma unroll
            for (int nj = 0; nj < 8; nj++) {
                const unsigned b0 = Vs[(8*ks + tig    ) * 72 + 8*nj + g];
                const unsigned b1 = Vs[(8*ks + tig + 4) * 72 + 8*nj + g];
                mma_tf32(o[nj], pa, b0, b1);
            }
        }
        __syncthreads();
    }

    // normalize + write g_ao as fp16 at fp16-16-group permuted positions
    const int b = bh / NHEADS, h = bh % NHEADS;
    const float inv0 = 1.f / l0, inv1 = 1.f / l1;
    const int r0 = qt * 128 + 16*warp + g;
    __half* ao0 = g_ao + ((size_t)b * SEQ + r0    ) * CDIM + h * HD;
    __half* ao1 = g_ao + ((size_t)b * SEQ + r0 + 8) * CDIM + h * HD;
    #pragma unroll
    for (int nj = 0; nj < 8; nj++) {
        const int j0  = 8*nj + 2*tig;          // even logical col within head
        const int kq  = j0 & 15;
        const int pos = (j0 & ~15) + 4*((kq & 7) >> 1) + 2*(kq >> 3);
        *(__half2*)&ao0[pos] = __floats2half2_rn(o[nj][0] * inv0, o[nj][1] * inv0);
        *(__half2*)&ao1[pos] = __floats2half2_rn(o[nj][2] * inv1, o[nj][3] * inv1);
    }
}

// ---------------------------------------------------------------------------
// Inputs (metadata order): x, qkv_w, qkv_b, proj_w, proj_b, H, W
// ---------------------------------------------------------------------------
extern "C" void kernel_launch(void* const* d_in, const int* in_sizes, int n_in,
                              void* d_out, int out_size)
{
    (void)in_sizes; (void)n_in; (void)out_size;
    const float* x      = (const float*)d_in[0];
    const float* qkv_w  = (const float*)d_in[1];
    const float* qkv_b  = (const float*)d_in[2];
    const float* proj_w = (const float*)d_in[3];
    const float* proj_b = (const float*)d_in[4];
    float* out = (float*)d_out;

    const int smem_gemm = 2 * (128*40 + 5120) * 4;                    // 81920 B
    const int smem_attn = (9216 + 2 * 9216) * (int)sizeof(unsigned);  // 110592 B
    cudaFuncSetAttribute((const void*)gemm_tc<0,4>, cudaFuncAttributeMaxDynamicSharedMemorySize, smem_gemm);
    cudaFuncSetAttribute((const void*)gemm_tc<1,4>, cudaFuncAttributeMaxDynamicSharedMemorySize, smem_gemm);
    cudaFuncSetAttribute((const void*)attn_tc,      cudaFuncAttributeMaxDynamicSharedMemorySize, smem_attn);

    // 0) fused pre-round (fp16 + 16-group k-interleave) + bias perm
    {
        const int ntot = GX16 + GW16 + GP16 + 3 * CDIM;
        pre_all<<<(ntot + 255) / 256, 256>>>(x, qkv_w, proj_w, qkv_b);
    }

    // 1) QKV GEMM (fp16) + bias -> per-head q/k/v (fp32 tf32-rounded; q x0.125)
    gemm_tc<0,4><<<dim3(3 * CDIM / 128, (BATCH * SEQ) / 128), 256, smem_gemm>>>(
        nullptr, nullptr, BATCH * SEQ, 3 * CDIM, CDIM);

    // 2) fused flash attention (tf32) -> g_ao (fp16, permuted)
    attn_tc<<<dim3(SEQ / 128, BHN), 256, smem_attn>>>();

    // 3) proj GEMM (fp16, BM=128 reverted per measurement) + bias -> d_out
    gemm_tc<1,4><<<dim3(CDIM / 128, (BATCH * SEQ) / 128), 256, smem_gemm>>>(
        proj_b, out, BATCH * SEQ, CDIM, CDIM);
}